// round 2
// baseline (speedup 1.0000x reference)
#include <cuda_runtime.h>

#define BATCH 2
#define NPTS  16384
#define KNN   24
#define DPTS  64
#define DM    128
#define PDIM  60
#define NP    (BATCH*NPTS)       /* 32768 query points   */
#define NR    (NP*KNN)           /* 786432 point-neighbor rows */
#define RES_ELEMS (NP*DM)        /* 4194304 */

/* ---- scratch (static device globals: allocation-free) ---- */
__device__ float d_x [NP*DM];                 /* 16 MB  : fc1 output      */
__device__ float d_pe[(size_t)NR*DM];         /* 402 MB : pos encoding    */
__device__ float d_t [(size_t)NR*DM];         /* 402 MB : relu(h@g1+b1)   */
__device__ float d_r [NP*DM];                 /* 16 MB  : pre-fc2 reduce  */

__constant__ float c_omega[10] = {
  1.0f, 0.398107170553497250f, 0.158489319246111348f, 0.063095734448019331f,
  0.025118864315095794f, 0.01f, 0.003981071705534973f, 0.001584893192461114f,
  0.000630957344480193f, 0.000251188643150958f };

/* =========================================================================
 * K1: x = features @ fc1_w + fc1_b            rows=32768, 64 -> 128
 * block = 256 thr, tile = 64 rows; thread (f, rg) owns 32 rows x 1 col
 * ========================================================================= */
__global__ void k_fc1(const float* __restrict__ feat,
                      const float* __restrict__ w,
                      const float* __restrict__ bias)
{
    extern __shared__ float sm[];
    float* ws = sm;               /* 64*128           */
    float* fs = sm + 64*128;      /* [64][68] feat^T  */
    int t = threadIdx.x, f = t & 127, rg = t >> 7, rb = rg * 32;
    for (int i = t; i < 64*128; i += 256) ws[i] = w[i];
    int r0 = blockIdx.x * 64;
    for (int idx = t; idx < 64*64; idx += 256) {
        int j = idx & 63, r = idx >> 6;
        fs[j*68 + r] = feat[(r0 + r)*64 + j];
    }
    __syncthreads();
    float b = bias[f];
    float acc[32];
#pragma unroll
    for (int i = 0; i < 32; i++) acc[i] = b;
#pragma unroll 2
    for (int j = 0; j < 64; j++) {
        float wv = ws[j*128 + f];
        const float4* rowp = (const float4*)(fs + j*68 + rb);
#pragma unroll
        for (int q = 0; q < 8; q++) {
            float4 v = rowp[q];
            acc[4*q+0] = fmaf(v.x, wv, acc[4*q+0]);
            acc[4*q+1] = fmaf(v.y, wv, acc[4*q+1]);
            acc[4*q+2] = fmaf(v.z, wv, acc[4*q+2]);
            acc[4*q+3] = fmaf(v.w, wv, acc[4*q+3]);
        }
    }
#pragma unroll
    for (int i = 0; i < 32; i++) d_x[(r0 + rb + i)*128 + f] = acc[i];
}

/* =========================================================================
 * K2 (fused): per 64-row tile of the (b,n,k) row space:
 *   e  = sincos_pos_embed(xyz[p] - knn_xyz[row])           [64][60]
 *   t1 = relu(e @ d1 + b1)                                 [64][128]
 *   pe = t1 @ d2 + b2                 -> d_pe              [64][128]
 *   h  = x[p] - x[knn] + pe
 *   t  = relu(h @ g1 + b3)            -> d_t               [64][128]
 * persistent: d1,d2,g1 stay smem-resident. 256 thr, 1 block/SM (208 KB smem)
 * ========================================================================= */
__global__ void k_main(const float* __restrict__ xyz,
                       const int*   __restrict__ knn_idx,
                       const float* __restrict__ knn_xyz,
                       const float* __restrict__ d1w, const float* __restrict__ d1b,
                       const float* __restrict__ d2w, const float* __restrict__ d2b,
                       const float* __restrict__ g1w, const float* __restrict__ g1b)
{
    extern __shared__ float sm[];
    float* d1s = sm;                  /* 60*128  =  7680 */
    float* d2s = d1s + 60*128;        /* 128*128 = 16384 */
    float* g1s = d2s + 128*128;       /* 128*128 = 16384 */
    float* es  = g1s + 128*128;       /* [60][68] =  4080 */
    float* hs  = es  + 60*68;         /* [128][68] = 8704 */
    int t = threadIdx.x, f = t & 127, rg = t >> 7, rb = rg * 32;
    for (int i = t; i < 60*128;  i += 256) d1s[i] = d1w[i];
    for (int i = t; i < 128*128; i += 256) d2s[i] = d2w[i];
    for (int i = t; i < 128*128; i += 256) g1s[i] = g1w[i];
    float b1 = d1b[f], b2 = d2b[f], b3 = g1b[f];
    __syncthreads();

    for (int tile = blockIdx.x; tile < NR/64; tile += gridDim.x) {
        int row0 = tile * 64;
        /* ---- sincos embedding: 192 threads, thread = (row, coord) ---- */
        if (t < 192) {
            int r = t & 63, c = t >> 6;
            int grow = row0 + r;
            int p = grow / KNN;
            float g = xyz[p*3 + c] - knn_xyz[(size_t)grow*3 + c];
#pragma unroll
            for (int j = 0; j < 10; j++) {
                float a = g * c_omega[j];
                es[(c*20 + j     )*68 + r] = __sinf(a);
                es[(c*20 + 10 + j)*68 + r] = __cosf(a);
            }
        }
        __syncthreads();

        /* ---- GEMM1: t1 = relu(e @ d1 + b1) -> hs (transposed) ---- */
        float acc[32];
#pragma unroll
        for (int i = 0; i < 32; i++) acc[i] = b1;
#pragma unroll 2
        for (int j = 0; j < 60; j++) {
            float wv = d1s[j*128 + f];
            const float4* rowp = (const float4*)(es + j*68 + rb);
#pragma unroll
            for (int q = 0; q < 8; q++) {
                float4 v = rowp[q];
                acc[4*q+0] = fmaf(v.x, wv, acc[4*q+0]);
                acc[4*q+1] = fmaf(v.y, wv, acc[4*q+1]);
                acc[4*q+2] = fmaf(v.z, wv, acc[4*q+2]);
                acc[4*q+3] = fmaf(v.w, wv, acc[4*q+3]);
            }
        }
#pragma unroll
        for (int i = 0; i < 32; i++) hs[f*68 + rb + i] = fmaxf(acc[i], 0.0f);
        __syncthreads();

        /* ---- GEMM2: pe = t1 @ d2 + b2 ---- */
        float pe[32];
#pragma unroll
        for (int i = 0; i < 32; i++) pe[i] = b2;
#pragma unroll 2
        for (int j = 0; j < 128; j++) {
            float wv = d2s[j*128 + f];
            const float4* rowp = (const float4*)(hs + j*68 + rb);
#pragma unroll
            for (int q = 0; q < 8; q++) {
                float4 v = rowp[q];
                pe[4*q+0] = fmaf(v.x, wv, pe[4*q+0]);
                pe[4*q+1] = fmaf(v.y, wv, pe[4*q+1]);
                pe[4*q+2] = fmaf(v.z, wv, pe[4*q+2]);
                pe[4*q+3] = fmaf(v.w, wv, pe[4*q+3]);
            }
        }
        __syncthreads();   /* all reads of t1 in hs are done */

        /* ---- write pe, build h = x[p] - x[knn] + pe into hs ---- */
#pragma unroll
        for (int i = 0; i < 32; i++) {
            int grow = row0 + rb + i;
            d_pe[(size_t)grow*128 + f] = pe[i];
            int p  = grow / KNN;
            int bb = p >> 14;                      /* p / NPTS */
            int gi = (bb << 14) + knn_idx[grow];
            float h = d_x[p*128 + f] - d_x[gi*128 + f] + pe[i];
            hs[f*68 + rb + i] = h;
        }
        __syncthreads();

        /* ---- GEMM3: t = relu(h @ g1 + b3) -> d_t ---- */
        float a3[32];
#pragma unroll
        for (int i = 0; i < 32; i++) a3[i] = b3;
#pragma unroll 2
        for (int j = 0; j < 128; j++) {
            float wv = g1s[j*128 + f];
            const float4* rowp = (const float4*)(hs + j*68 + rb);
#pragma unroll
            for (int q = 0; q < 8; q++) {
                float4 v = rowp[q];
                a3[4*q+0] = fmaf(v.x, wv, a3[4*q+0]);
                a3[4*q+1] = fmaf(v.y, wv, a3[4*q+1]);
                a3[4*q+2] = fmaf(v.z, wv, a3[4*q+2]);
                a3[4*q+3] = fmaf(v.w, wv, a3[4*q+3]);
            }
        }
#pragma unroll
        for (int i = 0; i < 32; i++)
            d_t[(size_t)(row0 + rb + i)*128 + f] = fmaxf(a3[i], 0.0f);
        __syncthreads();   /* tile buffers reused next iteration */
    }
}

/* =========================================================================
 * K3: per point p (128 thr = one channel each):
 *   logits = t @ g2 + b2 ; softmax over k ; attn -> d_out
 *   r[f]   = sum_k attn[k][f] * (x[knn] + pe)[k][f]   -> d_r
 * persistent, g2 smem-resident, 2 blocks/SM.
 * ========================================================================= */
__global__ void k_attn(const int* __restrict__ knn_idx,
                       const float* __restrict__ g2w, const float* __restrict__ g2b,
                       float* __restrict__ out_attn)
{
    extern __shared__ float sm[];
    float* g2s = sm;              /* 128*128  */
    float* ts  = sm + 128*128;    /* [128][28] t^T for one point */
    int f = threadIdx.x;
    for (int i = f; i < 128*128; i += 128) g2s[i] = g2w[i];
    float b = g2b[f];
    __syncthreads();
    const float scale = 0.0883883476483184406f;   /* 1/sqrt(128) */

    for (int p = blockIdx.x; p < NP; p += gridDim.x) {
        int base = p * KNN;
#pragma unroll
        for (int k = 0; k < KNN; k++)
            ts[f*28 + k] = d_t[(size_t)(base + k)*128 + f];
        __syncthreads();

        float acc[KNN];
#pragma unroll
        for (int k = 0; k < KNN; k++) acc[k] = b;
#pragma unroll 2
        for (int j = 0; j < 128; j++) {
            float wv = g2s[j*128 + f];
            const float4* rowp = (const float4*)(ts + j*28);
#pragma unroll
            for (int q = 0; q < 6; q++) {
                float4 v = rowp[q];
                acc[4*q+0] = fmaf(v.x, wv, acc[4*q+0]);
                acc[4*q+1] = fmaf(v.y, wv, acc[4*q+1]);
                acc[4*q+2] = fmaf(v.z, wv, acc[4*q+2]);
                acc[4*q+3] = fmaf(v.w, wv, acc[4*q+3]);
            }
        }
        /* softmax over k, fully in registers (thread owns channel f) */
        float m = -1e30f;
#pragma unroll
        for (int k = 0; k < KNN; k++) { acc[k] *= scale; m = fmaxf(m, acc[k]); }
        float s = 0.0f;
#pragma unroll
        for (int k = 0; k < KNN; k++) { acc[k] = __expf(acc[k] - m); s += acc[k]; }
        float inv = 1.0f / s;

        int bb = p >> 14;
        float rv = 0.0f;
#pragma unroll
        for (int k = 0; k < KNN; k++) {
            float a = acc[k] * inv;
            int grow = base + k;
            out_attn[(size_t)grow*128 + f] = a;
            int gi = (bb << 14) + knn_idx[grow];
            float wv = d_x[gi*128 + f] + d_pe[(size_t)grow*128 + f];
            rv = fmaf(a, wv, rv);
        }
        d_r[p*128 + f] = rv;
        __syncthreads();   /* before ts is overwritten for next point */
    }
}

/* =========================================================================
 * K4: res = r @ fc2 + fc2_b + x  -> d_out[0 .. NP*128)
 * ========================================================================= */
__global__ void k_fc2(const float* __restrict__ w, const float* __restrict__ bias,
                      float* __restrict__ out_res)
{
    extern __shared__ float sm[];
    float* ws = sm;               /* 128*128  */
    float* rs = sm + 128*128;     /* [128][68] */
    int t = threadIdx.x, f = t & 127, rg = t >> 7, rb = rg * 32;
    for (int i = t; i < 128*128; i += 256) ws[i] = w[i];
    int r0 = blockIdx.x * 64;
    for (int idx = t; idx < 64*128; idx += 256) {
        int j = idx & 127, r = idx >> 7;
        rs[j*68 + r] = d_r[(r0 + r)*128 + j];
    }
    __syncthreads();
    float b = bias[f];
    float acc[32];
#pragma unroll
    for (int i = 0; i < 32; i++) acc[i] = b;
#pragma unroll 2
    for (int j = 0; j < 128; j++) {
        float wv = ws[j*128 + f];
        const float4* rowp = (const float4*)(rs + j*68 + rb);
#pragma unroll
        for (int q = 0; q < 8; q++) {
            float4 v = rowp[q];
            acc[4*q+0] = fmaf(v.x, wv, acc[4*q+0]);
            acc[4*q+1] = fmaf(v.y, wv, acc[4*q+1]);
            acc[4*q+2] = fmaf(v.z, wv, acc[4*q+2]);
            acc[4*q+3] = fmaf(v.w, wv, acc[4*q+3]);
        }
    }
#pragma unroll
    for (int i = 0; i < 32; i++) {
        int row = r0 + rb + i;
        out_res[row*128 + f] = acc[i] + d_x[row*128 + f];
    }
}

/* ========================================================================= */
extern "C" void kernel_launch(void* const* d_in, const int* in_sizes, int n_in,
                              void* d_out, int out_size)
{
    const float* feat = (const float*)d_in[0];
    const float* xyz  = (const float*)d_in[1];
    const int*   knn  = (const int*  )d_in[2];
    const float* kxyz = (const float*)d_in[3];
    const float* fc1w = (const float*)d_in[4];
    const float* fc1b = (const float*)d_in[5];
    const float* fc2w = (const float*)d_in[6];
    const float* fc2b = (const float*)d_in[7];
    const float* d1w  = (const float*)d_in[8];
    const float* d1b  = (const float*)d_in[9];
    const float* d2w  = (const float*)d_in[10];
    const float* d2b  = (const float*)d_in[11];
    const float* g1w  = (const float*)d_in[12];
    const float* g1b  = (const float*)d_in[13];
    const float* g2w  = (const float*)d_in[14];
    const float* g2b  = (const float*)d_in[15];
    float* out = (float*)d_out;

    int sms = 148;
    cudaDeviceGetAttribute(&sms, cudaDevAttrMultiProcessorCount, 0);

    size_t sm1  = (size_t)(64*128 + 64*68) * 4;                              /* 50176  */
    size_t sm23 = (size_t)(60*128 + 2*128*128 + 60*68 + 128*68) * 4;         /* 212928 */
    size_t sm4  = (size_t)(128*128 + 128*28) * 4;                            /* 79872  */
    size_t sm5  = (size_t)(128*128 + 128*68) * 4;                            /* 100352 */

    cudaFuncSetAttribute(k_fc1,  cudaFuncAttributeMaxDynamicSharedMemorySize, (int)sm1);
    cudaFuncSetAttribute(k_main, cudaFuncAttributeMaxDynamicSharedMemorySize, (int)sm23);
    cudaFuncSetAttribute(k_attn, cudaFuncAttributeMaxDynamicSharedMemorySize, (int)sm4);
    cudaFuncSetAttribute(k_fc2,  cudaFuncAttributeMaxDynamicSharedMemorySize, (int)sm5);

    k_fc1 <<<NP/64, 256, sm1 >>>(feat, fc1w, fc1b);
    k_main<<<sms,   256, sm23>>>(xyz, knn, kxyz, d1w, d1b, d2w, d2b, g1w, g1b);
    k_attn<<<2*sms, 128, sm4 >>>(knn, g2w, g2b, out + RES_ELEMS);
    k_fc2 <<<NP/64, 256, sm5 >>>(fc2w, fc2b, out);
}

// round 3
// speedup vs baseline: 1.0064x; 1.0064x over previous
#include <cuda_runtime.h>

#define BATCH 2
#define NPTS  16384
#define KNN   24
#define DPTS  64
#define DM    128
#define PDIM  60
#define NP    (BATCH*NPTS)       /* 32768 query points   */
#define NR    (NP*KNN)           /* 786432 point-neighbor rows */
#define RES_ELEMS (NP*DM)        /* 4194304 */

/* ---- scratch (static device globals: allocation-free) ---- */
__device__ float d_x [NP*DM];                 /* 16 MB  : fc1 output      */
__device__ float d_pe[(size_t)NR*DM];         /* 402 MB : pos encoding    */
__device__ float d_t [(size_t)NR*DM];         /* 402 MB : relu(h@g1+b1)   */
__device__ float d_r [NP*DM];                 /* 16 MB  : pre-fc2 reduce  */

__constant__ float c_omega[10] = {
  1.0f, 0.398107170553497250f, 0.158489319246111348f, 0.063095734448019331f,
  0.025118864315095794f, 0.01f, 0.003981071705534973f, 0.001584893192461114f,
  0.000630957344480193f, 0.000251188643150958f };

/* =========================================================================
 * K1: x = features @ fc1_w + fc1_b            rows=32768, 64 -> 128
 * block = 256 thr, tile = 64 rows; thread (f, rg) owns 32 rows x 1 col
 * ========================================================================= */
__global__ void k_fc1(const float* __restrict__ feat,
                      const float* __restrict__ w,
                      const float* __restrict__ bias)
{
    extern __shared__ float sm[];
    float* ws = sm;               /* 64*128           */
    float* fs = sm + 64*128;      /* [64][68] feat^T  */
    int t = threadIdx.x, f = t & 127, rg = t >> 7, rb = rg * 32;
    for (int i = t; i < 64*128; i += 256) ws[i] = w[i];
    int r0 = blockIdx.x * 64;
    for (int idx = t; idx < 64*64; idx += 256) {
        int j = idx & 63, r = idx >> 6;
        fs[j*68 + r] = feat[(r0 + r)*64 + j];
    }
    __syncthreads();
    float b = bias[f];
    float acc[32];
#pragma unroll
    for (int i = 0; i < 32; i++) acc[i] = b;
#pragma unroll 2
    for (int j = 0; j < 64; j++) {
        float wv = ws[j*128 + f];
        const float4* rowp = (const float4*)(fs + j*68 + rb);
#pragma unroll
        for (int q = 0; q < 8; q++) {
            float4 v = rowp[q];
            acc[4*q+0] = fmaf(v.x, wv, acc[4*q+0]);
            acc[4*q+1] = fmaf(v.y, wv, acc[4*q+1]);
            acc[4*q+2] = fmaf(v.z, wv, acc[4*q+2]);
            acc[4*q+3] = fmaf(v.w, wv, acc[4*q+3]);
        }
    }
#pragma unroll
    for (int i = 0; i < 32; i++) d_x[(r0 + rb + i)*128 + f] = acc[i];
}

/* =========================================================================
 * K2 (fused): per 64-row tile of the (b,n,k) row space:
 *   e  = sincos_pos_embed(xyz[p] - knn_xyz[row])           [64][60]
 *   t1 = relu(e @ d1 + b1)                                 [64][128]
 *   pe = t1 @ d2 + b2                 -> d_pe              [64][128]
 *   h  = x[p] - x[knn] + pe
 *   t  = relu(h @ g1 + b3)            -> d_t               [64][128]
 * persistent: d1,d2,g1 stay smem-resident. 256 thr, 1 block/SM (208 KB smem)
 * ========================================================================= */
__global__ void k_main(const float* __restrict__ xyz,
                       const int*   __restrict__ knn_idx,
                       const float* __restrict__ knn_xyz,
                       const float* __restrict__ d1w, const float* __restrict__ d1b,
                       const float* __restrict__ d2w, const float* __restrict__ d2b,
                       const float* __restrict__ g1w, const float* __restrict__ g1b)
{
    extern __shared__ float sm[];
    float* d1s = sm;                  /* 60*128  =  7680 */
    float* d2s = d1s + 60*128;        /* 128*128 = 16384 */
    float* g1s = d2s + 128*128;       /* 128*128 = 16384 */
    float* es  = g1s + 128*128;       /* [60][68] =  4080 */
    float* hs  = es  + 60*68;         /* [128][68] = 8704 */
    int t = threadIdx.x, f = t & 127, rg = t >> 7, rb = rg * 32;
    for (int i = t; i < 60*128;  i += 256) d1s[i] = d1w[i];
    for (int i = t; i < 128*128; i += 256) d2s[i] = d2w[i];
    for (int i = t; i < 128*128; i += 256) g1s[i] = g1w[i];
    float b1 = d1b[f], b2 = d2b[f], b3 = g1b[f];
    __syncthreads();

    for (int tile = blockIdx.x; tile < NR/64; tile += gridDim.x) {
        int row0 = tile * 64;
        /* ---- sincos embedding: 192 threads, thread = (row, coord) ---- */
        if (t < 192) {
            int r = t & 63, c = t >> 6;
            int grow = row0 + r;
            int p = grow / KNN;
            float g = xyz[p*3 + c] - knn_xyz[(size_t)grow*3 + c];
#pragma unroll
            for (int j = 0; j < 10; j++) {
                float a = g * c_omega[j];
                es[(c*20 + j     )*68 + r] = __sinf(a);
                es[(c*20 + 10 + j)*68 + r] = __cosf(a);
            }
        }
        __syncthreads();

        /* ---- GEMM1: t1 = relu(e @ d1 + b1) -> hs (transposed) ---- */
        float acc[32];
#pragma unroll
        for (int i = 0; i < 32; i++) acc[i] = b1;
#pragma unroll 2
        for (int j = 0; j < 60; j++) {
            float wv = d1s[j*128 + f];
            const float4* rowp = (const float4*)(es + j*68 + rb);
#pragma unroll
            for (int q = 0; q < 8; q++) {
                float4 v = rowp[q];
                acc[4*q+0] = fmaf(v.x, wv, acc[4*q+0]);
                acc[4*q+1] = fmaf(v.y, wv, acc[4*q+1]);
                acc[4*q+2] = fmaf(v.z, wv, acc[4*q+2]);
                acc[4*q+3] = fmaf(v.w, wv, acc[4*q+3]);
            }
        }
#pragma unroll
        for (int i = 0; i < 32; i++) hs[f*68 + rb + i] = fmaxf(acc[i], 0.0f);
        __syncthreads();

        /* ---- GEMM2: pe = t1 @ d2 + b2 ---- */
        float pe[32];
#pragma unroll
        for (int i = 0; i < 32; i++) pe[i] = b2;
#pragma unroll 2
        for (int j = 0; j < 128; j++) {
            float wv = d2s[j*128 + f];
            const float4* rowp = (const float4*)(hs + j*68 + rb);
#pragma unroll
            for (int q = 0; q < 8; q++) {
                float4 v = rowp[q];
                pe[4*q+0] = fmaf(v.x, wv, pe[4*q+0]);
                pe[4*q+1] = fmaf(v.y, wv, pe[4*q+1]);
                pe[4*q+2] = fmaf(v.z, wv, pe[4*q+2]);
                pe[4*q+3] = fmaf(v.w, wv, pe[4*q+3]);
            }
        }
        __syncthreads();   /* all reads of t1 in hs are done */

        /* ---- write pe, build h = x[p] - x[knn] + pe into hs ---- */
#pragma unroll
        for (int i = 0; i < 32; i++) {
            int grow = row0 + rb + i;
            d_pe[(size_t)grow*128 + f] = pe[i];
            int p  = grow / KNN;
            int bb = p >> 14;                      /* p / NPTS */
            int gi = (bb << 14) + knn_idx[grow];
            float h = d_x[p*128 + f] - d_x[gi*128 + f] + pe[i];
            hs[f*68 + rb + i] = h;
        }
        __syncthreads();

        /* ---- GEMM3: t = relu(h @ g1 + b3) -> d_t ---- */
        float a3[32];
#pragma unroll
        for (int i = 0; i < 32; i++) a3[i] = b3;
#pragma unroll 2
        for (int j = 0; j < 128; j++) {
            float wv = g1s[j*128 + f];
            const float4* rowp = (const float4*)(hs + j*68 + rb);
#pragma unroll
            for (int q = 0; q < 8; q++) {
                float4 v = rowp[q];
                a3[4*q+0] = fmaf(v.x, wv, a3[4*q+0]);
                a3[4*q+1] = fmaf(v.y, wv, a3[4*q+1]);
                a3[4*q+2] = fmaf(v.z, wv, a3[4*q+2]);
                a3[4*q+3] = fmaf(v.w, wv, a3[4*q+3]);
            }
        }
#pragma unroll
        for (int i = 0; i < 32; i++)
            d_t[(size_t)(row0 + rb + i)*128 + f] = fmaxf(a3[i], 0.0f);
        __syncthreads();   /* tile buffers reused next iteration */
    }
}

/* =========================================================================
 * K3: per point p (128 thr = one channel each):
 *   logits = t @ g2 + b2 ; softmax over k ; attn -> d_out
 *   r[f]   = sum_k attn[k][f] * (x[knn] + pe)[k][f]   -> d_r
 * persistent, g2 smem-resident, 2 blocks/SM.
 * ========================================================================= */
__global__ void k_attn(const int* __restrict__ knn_idx,
                       const float* __restrict__ g2w, const float* __restrict__ g2b,
                       float* __restrict__ out_attn)
{
    extern __shared__ float sm[];
    float* g2s = sm;              /* 128*128  */
    float* ts  = sm + 128*128;    /* [128][28] t^T for one point */
    int f = threadIdx.x;
    for (int i = f; i < 128*128; i += 128) g2s[i] = g2w[i];
    float b = g2b[f];
    __syncthreads();
    const float scale = 0.0883883476483184406f;   /* 1/sqrt(128) */

    for (int p = blockIdx.x; p < NP; p += gridDim.x) {
        int base = p * KNN;
#pragma unroll
        for (int k = 0; k < KNN; k++)
            ts[f*28 + k] = d_t[(size_t)(base + k)*128 + f];
        __syncthreads();

        float acc[KNN];
#pragma unroll
        for (int k = 0; k < KNN; k++) acc[k] = b;
#pragma unroll 2
        for (int j = 0; j < 128; j++) {
            float wv = g2s[j*128 + f];
            const float4* rowp = (const float4*)(ts + j*28);
#pragma unroll
            for (int q = 0; q < 6; q++) {
                float4 v = rowp[q];
                acc[4*q+0] = fmaf(v.x, wv, acc[4*q+0]);
                acc[4*q+1] = fmaf(v.y, wv, acc[4*q+1]);
                acc[4*q+2] = fmaf(v.z, wv, acc[4*q+2]);
                acc[4*q+3] = fmaf(v.w, wv, acc[4*q+3]);
            }
        }
        /* softmax over k, fully in registers (thread owns channel f) */
        float m = -1e30f;
#pragma unroll
        for (int k = 0; k < KNN; k++) { acc[k] *= scale; m = fmaxf(m, acc[k]); }
        float s = 0.0f;
#pragma unroll
        for (int k = 0; k < KNN; k++) { acc[k] = __expf(acc[k] - m); s += acc[k]; }
        float inv = 1.0f / s;

        int bb = p >> 14;
        float rv = 0.0f;
#pragma unroll
        for (int k = 0; k < KNN; k++) {
            float a = acc[k] * inv;
            int grow = base + k;
            out_attn[(size_t)grow*128 + f] = a;
            int gi = (bb << 14) + knn_idx[grow];
            float wv = d_x[gi*128 + f] + d_pe[(size_t)grow*128 + f];
            rv = fmaf(a, wv, rv);
        }
        d_r[p*128 + f] = rv;
        __syncthreads();   /* before ts is overwritten for next point */
    }
}

/* =========================================================================
 * K4: res = r @ fc2 + fc2_b + x  -> d_out[0 .. NP*128)
 * ========================================================================= */
__global__ void k_fc2(const float* __restrict__ w, const float* __restrict__ bias,
                      float* __restrict__ out_res)
{
    extern __shared__ float sm[];
    float* ws = sm;               /* 128*128  */
    float* rs = sm + 128*128;     /* [128][68] */
    int t = threadIdx.x, f = t & 127, rg = t >> 7, rb = rg * 32;
    for (int i = t; i < 128*128; i += 256) ws[i] = w[i];
    int r0 = blockIdx.x * 64;
    for (int idx = t; idx < 64*128; idx += 256) {
        int j = idx & 127, r = idx >> 7;
        rs[j*68 + r] = d_r[(r0 + r)*128 + j];
    }
    __syncthreads();
    float b = bias[f];
    float acc[32];
#pragma unroll
    for (int i = 0; i < 32; i++) acc[i] = b;
#pragma unroll 2
    for (int j = 0; j < 128; j++) {
        float wv = ws[j*128 + f];
        const float4* rowp = (const float4*)(rs + j*68 + rb);
#pragma unroll
        for (int q = 0; q < 8; q++) {
            float4 v = rowp[q];
            acc[4*q+0] = fmaf(v.x, wv, acc[4*q+0]);
            acc[4*q+1] = fmaf(v.y, wv, acc[4*q+1]);
            acc[4*q+2] = fmaf(v.z, wv, acc[4*q+2]);
            acc[4*q+3] = fmaf(v.w, wv, acc[4*q+3]);
        }
    }
#pragma unroll
    for (int i = 0; i < 32; i++) {
        int row = r0 + rb + i;
        out_res[row*128 + f] = acc[i] + d_x[row*128 + f];
    }
}

/* ========================================================================= */
extern "C" void kernel_launch(void* const* d_in, const int* in_sizes, int n_in,
                              void* d_out, int out_size)
{
    const float* feat = (const float*)d_in[0];
    const float* xyz  = (const float*)d_in[1];
    const int*   knn  = (const int*  )d_in[2];
    const float* kxyz = (const float*)d_in[3];
    const float* fc1w = (const float*)d_in[4];
    const float* fc1b = (const float*)d_in[5];
    const float* fc2w = (const float*)d_in[6];
    const float* fc2b = (const float*)d_in[7];
    const float* d1w  = (const float*)d_in[8];
    const float* d1b  = (const float*)d_in[9];
    const float* d2w  = (const float*)d_in[10];
    const float* d2b  = (const float*)d_in[11];
    const float* g1w  = (const float*)d_in[12];
    const float* g1b  = (const float*)d_in[13];
    const float* g2w  = (const float*)d_in[14];
    const float* g2b  = (const float*)d_in[15];
    float* out = (float*)d_out;

    int sms = 148;
    cudaDeviceGetAttribute(&sms, cudaDevAttrMultiProcessorCount, 0);

    size_t sm1  = (size_t)(64*128 + 64*68) * 4;                              /* 50176  */
    size_t sm23 = (size_t)(60*128 + 2*128*128 + 60*68 + 128*68) * 4;         /* 212928 */
    size_t sm4  = (size_t)(128*128 + 128*28) * 4;                            /* 79872  */
    size_t sm5  = (size_t)(128*128 + 128*68) * 4;                            /* 100352 */

    cudaFuncSetAttribute(k_fc1,  cudaFuncAttributeMaxDynamicSharedMemorySize, (int)sm1);
    cudaFuncSetAttribute(k_main, cudaFuncAttributeMaxDynamicSharedMemorySize, (int)sm23);
    cudaFuncSetAttribute(k_attn, cudaFuncAttributeMaxDynamicSharedMemorySize, (int)sm4);
    cudaFuncSetAttribute(k_fc2,  cudaFuncAttributeMaxDynamicSharedMemorySize, (int)sm5);

    k_fc1 <<<NP/64, 256, sm1 >>>(feat, fc1w, fc1b);
    k_main<<<sms,   256, sm23>>>(xyz, knn, kxyz, d1w, d1b, d2w, d2b, g1w, g1b);
    k_attn<<<2*sms, 128, sm4 >>>(knn, g2w, g2b, out + RES_ELEMS);
    k_fc2 <<<NP/64, 256, sm5 >>>(fc2w, fc2b, out);
}

// round 4
// speedup vs baseline: 1.0073x; 1.0009x over previous
#include <cuda_runtime.h>

#define BATCH 2
#define NPTS  16384
#define KNN   24
#define DPTS  64
#define DM    128
#define PDIM  60
#define NP    (BATCH*NPTS)       /* 32768 query points   */
#define NR    (NP*KNN)           /* 786432 point-neighbor rows */
#define RES_ELEMS (NP*DM)        /* 4194304 */

/* ---- scratch (static device globals: allocation-free) ---- */
__device__ float d_x [NP*DM];                 /* 16 MB  : fc1 output      */
__device__ float d_pe[(size_t)NR*DM];         /* 402 MB : pos encoding    */
__device__ float d_t [(size_t)NR*DM];         /* 402 MB : relu(h@g1+b1)   */
__device__ float d_r [NP*DM];                 /* 16 MB  : pre-fc2 reduce  */

__constant__ float c_omega[10] = {
  1.0f, 0.398107170553497250f, 0.158489319246111348f, 0.063095734448019331f,
  0.025118864315095794f, 0.01f, 0.003981071705534973f, 0.001584893192461114f,
  0.000630957344480193f, 0.000251188643150958f };

/* =========================================================================
 * K1: x = features @ fc1_w + fc1_b            rows=32768, 64 -> 128
 * block = 256 thr, tile = 64 rows; thread (f, rg) owns 32 rows x 1 col
 * ========================================================================= */
__global__ void k_fc1(const float* __restrict__ feat,
                      const float* __restrict__ w,
                      const float* __restrict__ bias)
{
    extern __shared__ float sm[];
    float* ws = sm;               /* 64*128           */
    float* fs = sm + 64*128;      /* [64][68] feat^T  */
    int t = threadIdx.x, f = t & 127, rg = t >> 7, rb = rg * 32;
    for (int i = t; i < 64*128; i += 256) ws[i] = w[i];
    int r0 = blockIdx.x * 64;
    for (int idx = t; idx < 64*64; idx += 256) {
        int j = idx & 63, r = idx >> 6;
        fs[j*68 + r] = feat[(r0 + r)*64 + j];
    }
    __syncthreads();
    float b = bias[f];
    float acc[32];
#pragma unroll
    for (int i = 0; i < 32; i++) acc[i] = b;
#pragma unroll 2
    for (int j = 0; j < 64; j++) {
        float wv = ws[j*128 + f];
        const float4* rowp = (const float4*)(fs + j*68 + rb);
#pragma unroll
        for (int q = 0; q < 8; q++) {
            float4 v = rowp[q];
            acc[4*q+0] = fmaf(v.x, wv, acc[4*q+0]);
            acc[4*q+1] = fmaf(v.y, wv, acc[4*q+1]);
            acc[4*q+2] = fmaf(v.z, wv, acc[4*q+2]);
            acc[4*q+3] = fmaf(v.w, wv, acc[4*q+3]);
        }
    }
#pragma unroll
    for (int i = 0; i < 32; i++) d_x[(r0 + rb + i)*128 + f] = acc[i];
}

/* =========================================================================
 * K2 (fused): per 64-row tile of the (b,n,k) row space:
 *   e  = sincos_pos_embed(xyz[p] - knn_xyz[row])           [64][60]
 *   t1 = relu(e @ d1 + b1)                                 [64][128]
 *   pe = t1 @ d2 + b2                 -> d_pe              [64][128]
 *   h  = x[p] - x[knn] + pe
 *   t  = relu(h @ g1 + b3)            -> d_t               [64][128]
 * persistent: d1,d2,g1 stay smem-resident. 256 thr, 1 block/SM (208 KB smem)
 * ========================================================================= */
__global__ void k_main(const float* __restrict__ xyz,
                       const int*   __restrict__ knn_idx,
                       const float* __restrict__ knn_xyz,
                       const float* __restrict__ d1w, const float* __restrict__ d1b,
                       const float* __restrict__ d2w, const float* __restrict__ d2b,
                       const float* __restrict__ g1w, const float* __restrict__ g1b)
{
    extern __shared__ float sm[];
    float* d1s = sm;                  /* 60*128  =  7680 */
    float* d2s = d1s + 60*128;        /* 128*128 = 16384 */
    float* g1s = d2s + 128*128;       /* 128*128 = 16384 */
    float* es  = g1s + 128*128;       /* [60][68] =  4080 */
    float* hs  = es  + 60*68;         /* [128][68] = 8704 */
    int t = threadIdx.x, f = t & 127, rg = t >> 7, rb = rg * 32;
    for (int i = t; i < 60*128;  i += 256) d1s[i] = d1w[i];
    for (int i = t; i < 128*128; i += 256) d2s[i] = d2w[i];
    for (int i = t; i < 128*128; i += 256) g1s[i] = g1w[i];
    float b1 = d1b[f], b2 = d2b[f], b3 = g1b[f];
    __syncthreads();

    for (int tile = blockIdx.x; tile < NR/64; tile += gridDim.x) {
        int row0 = tile * 64;
        /* ---- sincos embedding: 192 threads, thread = (row, coord) ---- */
        if (t < 192) {
            int r = t & 63, c = t >> 6;
            int grow = row0 + r;
            int p = grow / KNN;
            float g = xyz[p*3 + c] - knn_xyz[(size_t)grow*3 + c];
#pragma unroll
            for (int j = 0; j < 10; j++) {
                float a = g * c_omega[j];
                es[(c*20 + j     )*68 + r] = __sinf(a);
                es[(c*20 + 10 + j)*68 + r] = __cosf(a);
            }
        }
        __syncthreads();

        /* ---- GEMM1: t1 = relu(e @ d1 + b1) -> hs (transposed) ---- */
        float acc[32];
#pragma unroll
        for (int i = 0; i < 32; i++) acc[i] = b1;
#pragma unroll 2
        for (int j = 0; j < 60; j++) {
            float wv = d1s[j*128 + f];
            const float4* rowp = (const float4*)(es + j*68 + rb);
#pragma unroll
            for (int q = 0; q < 8; q++) {
                float4 v = rowp[q];
                acc[4*q+0] = fmaf(v.x, wv, acc[4*q+0]);
                acc[4*q+1] = fmaf(v.y, wv, acc[4*q+1]);
                acc[4*q+2] = fmaf(v.z, wv, acc[4*q+2]);
                acc[4*q+3] = fmaf(v.w, wv, acc[4*q+3]);
            }
        }
#pragma unroll
        for (int i = 0; i < 32; i++) hs[f*68 + rb + i] = fmaxf(acc[i], 0.0f);
        __syncthreads();

        /* ---- GEMM2: pe = t1 @ d2 + b2 ---- */
        float pe[32];
#pragma unroll
        for (int i = 0; i < 32; i++) pe[i] = b2;
#pragma unroll 2
        for (int j = 0; j < 128; j++) {
            float wv = d2s[j*128 + f];
            const float4* rowp = (const float4*)(hs + j*68 + rb);
#pragma unroll
            for (int q = 0; q < 8; q++) {
                float4 v = rowp[q];
                pe[4*q+0] = fmaf(v.x, wv, pe[4*q+0]);
                pe[4*q+1] = fmaf(v.y, wv, pe[4*q+1]);
                pe[4*q+2] = fmaf(v.z, wv, pe[4*q+2]);
                pe[4*q+3] = fmaf(v.w, wv, pe[4*q+3]);
            }
        }
        __syncthreads();   /* all reads of t1 in hs are done */

        /* ---- write pe, build h = x[p] - x[knn] + pe into hs ---- */
#pragma unroll
        for (int i = 0; i < 32; i++) {
            int grow = row0 + rb + i;
            d_pe[(size_t)grow*128 + f] = pe[i];
            int p  = grow / KNN;
            int bb = p >> 14;                      /* p / NPTS */
            int gi = (bb << 14) + knn_idx[grow];
            float h = d_x[p*128 + f] - d_x[gi*128 + f] + pe[i];
            hs[f*68 + rb + i] = h;
        }
        __syncthreads();

        /* ---- GEMM3: t = relu(h @ g1 + b3) -> d_t ---- */
        float a3[32];
#pragma unroll
        for (int i = 0; i < 32; i++) a3[i] = b3;
#pragma unroll 2
        for (int j = 0; j < 128; j++) {
            float wv = g1s[j*128 + f];
            const float4* rowp = (const float4*)(hs + j*68 + rb);
#pragma unroll
            for (int q = 0; q < 8; q++) {
                float4 v = rowp[q];
                a3[4*q+0] = fmaf(v.x, wv, a3[4*q+0]);
                a3[4*q+1] = fmaf(v.y, wv, a3[4*q+1]);
                a3[4*q+2] = fmaf(v.z, wv, a3[4*q+2]);
                a3[4*q+3] = fmaf(v.w, wv, a3[4*q+3]);
            }
        }
#pragma unroll
        for (int i = 0; i < 32; i++)
            d_t[(size_t)(row0 + rb + i)*128 + f] = fmaxf(a3[i], 0.0f);
        __syncthreads();   /* tile buffers reused next iteration */
    }
}

/* =========================================================================
 * K3: per point p (128 thr = one channel each):
 *   logits = t @ g2 + b2 ; softmax over k ; attn -> d_out
 *   r[f]   = sum_k attn[k][f] * (x[knn] + pe)[k][f]   -> d_r
 * persistent, g2 smem-resident, 2 blocks/SM.
 * ========================================================================= */
__global__ void k_attn(const int* __restrict__ knn_idx,
                       const float* __restrict__ g2w, const float* __restrict__ g2b,
                       float* __restrict__ out_attn)
{
    extern __shared__ float sm[];
    float* g2s = sm;              /* 128*128  */
    float* ts  = sm + 128*128;    /* [128][28] t^T for one point */
    int f = threadIdx.x;
    for (int i = f; i < 128*128; i += 128) g2s[i] = g2w[i];
    float b = g2b[f];
    __syncthreads();
    const float scale = 0.0883883476483184406f;   /* 1/sqrt(128) */

    for (int p = blockIdx.x; p < NP; p += gridDim.x) {
        int base = p * KNN;
#pragma unroll
        for (int k = 0; k < KNN; k++)
            ts[f*28 + k] = d_t[(size_t)(base + k)*128 + f];
        __syncthreads();

        float acc[KNN];
#pragma unroll
        for (int k = 0; k < KNN; k++) acc[k] = b;
#pragma unroll 2
        for (int j = 0; j < 128; j++) {
            float wv = g2s[j*128 + f];
            const float4* rowp = (const float4*)(ts + j*28);
#pragma unroll
            for (int q = 0; q < 6; q++) {
                float4 v = rowp[q];
                acc[4*q+0] = fmaf(v.x, wv, acc[4*q+0]);
                acc[4*q+1] = fmaf(v.y, wv, acc[4*q+1]);
                acc[4*q+2] = fmaf(v.z, wv, acc[4*q+2]);
                acc[4*q+3] = fmaf(v.w, wv, acc[4*q+3]);
            }
        }
        /* softmax over k, fully in registers (thread owns channel f) */
        float m = -1e30f;
#pragma unroll
        for (int k = 0; k < KNN; k++) { acc[k] *= scale; m = fmaxf(m, acc[k]); }
        float s = 0.0f;
#pragma unroll
        for (int k = 0; k < KNN; k++) { acc[k] = __expf(acc[k] - m); s += acc[k]; }
        float inv = 1.0f / s;

        int bb = p >> 14;
        float rv = 0.0f;
#pragma unroll
        for (int k = 0; k < KNN; k++) {
            float a = acc[k] * inv;
            int grow = base + k;
            out_attn[(size_t)grow*128 + f] = a;
            int gi = (bb << 14) + knn_idx[grow];
            float wv = d_x[gi*128 + f] + d_pe[(size_t)grow*128 + f];
            rv = fmaf(a, wv, rv);
        }
        d_r[p*128 + f] = rv;
        __syncthreads();   /* before ts is overwritten for next point */
    }
}

/* =========================================================================
 * K4: res = r @ fc2 + fc2_b + x  -> d_out[0 .. NP*128)
 * ========================================================================= */
__global__ void k_fc2(const float* __restrict__ w, const float* __restrict__ bias,
                      float* __restrict__ out_res)
{
    extern __shared__ float sm[];
    float* ws = sm;               /* 128*128  */
    float* rs = sm + 128*128;     /* [128][68] */
    int t = threadIdx.x, f = t & 127, rg = t >> 7, rb = rg * 32;
    for (int i = t; i < 128*128; i += 256) ws[i] = w[i];
    int r0 = blockIdx.x * 64;
    for (int idx = t; idx < 64*128; idx += 256) {
        int j = idx & 127, r = idx >> 7;
        rs[j*68 + r] = d_r[(r0 + r)*128 + j];
    }
    __syncthreads();
    float b = bias[f];
    float acc[32];
#pragma unroll
    for (int i = 0; i < 32; i++) acc[i] = b;
#pragma unroll 2
    for (int j = 0; j < 128; j++) {
        float wv = ws[j*128 + f];
        const float4* rowp = (const float4*)(rs + j*68 + rb);
#pragma unroll
        for (int q = 0; q < 8; q++) {
            float4 v = rowp[q];
            acc[4*q+0] = fmaf(v.x, wv, acc[4*q+0]);
            acc[4*q+1] = fmaf(v.y, wv, acc[4*q+1]);
            acc[4*q+2] = fmaf(v.z, wv, acc[4*q+2]);
            acc[4*q+3] = fmaf(v.w, wv, acc[4*q+3]);
        }
    }
#pragma unroll
    for (int i = 0; i < 32; i++) {
        int row = r0 + rb + i;
        out_res[row*128 + f] = acc[i] + d_x[row*128 + f];
    }
}

/* ========================================================================= */
extern "C" void kernel_launch(void* const* d_in, const int* in_sizes, int n_in,
                              void* d_out, int out_size)
{
    const float* feat = (const float*)d_in[0];
    const float* xyz  = (const float*)d_in[1];
    const int*   knn  = (const int*  )d_in[2];
    const float* kxyz = (const float*)d_in[3];
    const float* fc1w = (const float*)d_in[4];
    const float* fc1b = (const float*)d_in[5];
    const float* fc2w = (const float*)d_in[6];
    const float* fc2b = (const float*)d_in[7];
    const float* d1w  = (const float*)d_in[8];
    const float* d1b  = (const float*)d_in[9];
    const float* d2w  = (const float*)d_in[10];
    const float* d2b  = (const float*)d_in[11];
    const float* g1w  = (const float*)d_in[12];
    const float* g1b  = (const float*)d_in[13];
    const float* g2w  = (const float*)d_in[14];
    const float* g2b  = (const float*)d_in[15];
    float* out = (float*)d_out;

    int sms = 148;
    cudaDeviceGetAttribute(&sms, cudaDevAttrMultiProcessorCount, 0);

    size_t sm1  = (size_t)(64*128 + 64*68) * 4;                              /* 50176  */
    size_t sm23 = (size_t)(60*128 + 2*128*128 + 60*68 + 128*68) * 4;         /* 212928 */
    size_t sm4  = (size_t)(128*128 + 128*28) * 4;                            /* 79872  */
    size_t sm5  = (size_t)(128*128 + 128*68) * 4;                            /* 100352 */

    cudaFuncSetAttribute(k_fc1,  cudaFuncAttributeMaxDynamicSharedMemorySize, (int)sm1);
    cudaFuncSetAttribute(k_main, cudaFuncAttributeMaxDynamicSharedMemorySize, (int)sm23);
    cudaFuncSetAttribute(k_attn, cudaFuncAttributeMaxDynamicSharedMemorySize, (int)sm4);
    cudaFuncSetAttribute(k_fc2,  cudaFuncAttributeMaxDynamicSharedMemorySize, (int)sm5);

    k_fc1 <<<NP/64, 256, sm1 >>>(feat, fc1w, fc1b);
    k_main<<<sms,   256, sm23>>>(xyz, knn, kxyz, d1w, d1b, d2w, d2b, g1w, g1b);
    k_attn<<<2*sms, 128, sm4 >>>(knn, g2w, g2b, out + RES_ELEMS);
    k_fc2 <<<NP/64, 256, sm5 >>>(fc2w, fc2b, out);
}